// round 4
// baseline (speedup 1.0000x reference)
#include <cuda_runtime.h>

#define BB 512   // batch
#define TT 256   // seq len
#define HH 64    // hidden
#define GG 256   // 4*H gates
#define DD 64    // input/output dim

// Scratch (static __device__ arrays — allocation-free per harness rules)
__device__ float g_xg[(size_t)TT * BB * GG];   // gate pre-activations [T][B][G]
__device__ float g_hseq[(size_t)TT * BB * HH]; // hidden sequence [T][B][H]
__device__ float g_lat[BB * HH];               // encoder latent [B][H]
__device__ float g_xgc[BB * GG];               // dec0 constant xg [B][G]

typedef unsigned long long u64;

__device__ __forceinline__ u64 ffma2(u64 a, u64 b, u64 c) {
    u64 d;
    asm("fma.rn.f32x2 %0, %1, %2, %3;" : "=l"(d) : "l"(a), "l"(b), "l"(c));
    return d;
}
__device__ __forceinline__ float2 up2(u64 v) {
    float lo, hi;
    asm("mov.b64 {%0, %1}, %2;" : "=f"(lo), "=f"(hi) : "l"(v));
    return make_float2(lo, hi);
}

__device__ __forceinline__ float fsigm(float x) {
    return __fdividef(1.0f, 1.0f + __expf(-x));
}
__device__ __forceinline__ float ftanh(float x) {
    return 1.0f - __fdividef(2.0f, __expf(2.0f * x) + 1.0f);
}

// ---------------------------------------------------------------------------
// xg GEMM: out[n][g] = sum_k X[b(n),t(n)][k] * W[g][k] + bih[g] + bhh[g]
// n = t*BB + b. X element offset = b*st_b + t*st_t + k. K = 64 fixed.
// ---------------------------------------------------------------------------
__global__ __launch_bounds__(256) void xg_gemm(
    const float* __restrict__ X, int st_b, int st_t,
    const float* __restrict__ W,
    const float* __restrict__ bih, const float* __restrict__ bhh,
    float* __restrict__ out)
{
    __shared__ float Xs[64][128];  // [k][m]
    __shared__ float Ws[64][64];   // [k][g]
    const int tid  = threadIdx.x;
    const int row0 = blockIdx.x * 128;
    const int col0 = blockIdx.y * 64;

    #pragma unroll
    for (int i = 0; i < 8; i++) {
        int idx = tid + i * 256;
        int m   = idx & 127;
        int k4  = idx >> 7;
        int n   = row0 + m;
        int b   = n & (BB - 1);
        int t   = n >> 9;
        float4 v = *(const float4*)(X + (size_t)b * st_b + (size_t)t * st_t + k4 * 4);
        Xs[k4*4+0][m] = v.x; Xs[k4*4+1][m] = v.y;
        Xs[k4*4+2][m] = v.z; Xs[k4*4+3][m] = v.w;
    }
    #pragma unroll
    for (int i = 0; i < 4; i++) {
        int idx = tid + i * 256;
        int m   = idx & 63;
        int k4  = idx >> 6;
        float4 v = *(const float4*)(W + (size_t)(col0 + m) * 64 + k4 * 4);
        Ws[k4*4+0][m] = v.x; Ws[k4*4+1][m] = v.y;
        Ws[k4*4+2][m] = v.z; Ws[k4*4+3][m] = v.w;
    }
    __syncthreads();

    const int tx = tid & 15;
    const int ty = tid >> 4;

    float4 bi = *(const float4*)(bih + col0 + tx * 4);
    float4 bh = *(const float4*)(bhh + col0 + tx * 4);
    const float bs0 = bi.x + bh.x, bs1 = bi.y + bh.y;
    const float bs2 = bi.z + bh.z, bs3 = bi.w + bh.w;

    float acc[8][4];
    #pragma unroll
    for (int r = 0; r < 8; r++) {
        acc[r][0] = bs0; acc[r][1] = bs1; acc[r][2] = bs2; acc[r][3] = bs3;
    }

    #pragma unroll 16
    for (int k = 0; k < 64; k++) {
        float4 a0 = *(const float4*)&Xs[k][ty * 8];
        float4 a1 = *(const float4*)&Xs[k][ty * 8 + 4];
        float4 wv = *(const float4*)&Ws[k][tx * 4];
        float a[8] = {a0.x, a0.y, a0.z, a0.w, a1.x, a1.y, a1.z, a1.w};
        #pragma unroll
        for (int r = 0; r < 8; r++) {
            acc[r][0] = fmaf(a[r], wv.x, acc[r][0]);
            acc[r][1] = fmaf(a[r], wv.y, acc[r][1]);
            acc[r][2] = fmaf(a[r], wv.z, acc[r][2]);
            acc[r][3] = fmaf(a[r], wv.w, acc[r][3]);
        }
    }
    #pragma unroll
    for (int r = 0; r < 8; r++) {
        float4 o = make_float4(acc[r][0], acc[r][1], acc[r][2], acc[r][3]);
        *(float4*)(out + (size_t)(row0 + ty * 8 + r) * GG + col0 + tx * 4) = o;
    }
}

// ---------------------------------------------------------------------------
// FC GEMM: out[b][t][d] = hseq_row(n=t*BB+b) . fcW[d] + fcb[d]
// ---------------------------------------------------------------------------
__global__ __launch_bounds__(256) void fc_gemm(
    const float* __restrict__ X,
    const float* __restrict__ W,
    const float* __restrict__ bias,
    float* __restrict__ out)
{
    __shared__ float Xs[64][128];
    __shared__ float Ws[64][64];
    const int tid  = threadIdx.x;
    const int row0 = blockIdx.x * 128;

    #pragma unroll
    for (int i = 0; i < 8; i++) {
        int idx = tid + i * 256;
        int m   = idx & 127;
        int k4  = idx >> 7;
        float4 v = *(const float4*)(X + (size_t)(row0 + m) * 64 + k4 * 4);
        Xs[k4*4+0][m] = v.x; Xs[k4*4+1][m] = v.y;
        Xs[k4*4+2][m] = v.z; Xs[k4*4+3][m] = v.w;
    }
    #pragma unroll
    for (int i = 0; i < 4; i++) {
        int idx = tid + i * 256;
        int m   = idx & 63;
        int k4  = idx >> 6;
        float4 v = *(const float4*)(W + (size_t)m * 64 + k4 * 4);
        Ws[k4*4+0][m] = v.x; Ws[k4*4+1][m] = v.y;
        Ws[k4*4+2][m] = v.z; Ws[k4*4+3][m] = v.w;
    }
    __syncthreads();

    const int tx = tid & 15;
    const int ty = tid >> 4;

    float4 bv = *(const float4*)(bias + tx * 4);
    float acc[8][4];
    #pragma unroll
    for (int r = 0; r < 8; r++) {
        acc[r][0] = bv.x; acc[r][1] = bv.y; acc[r][2] = bv.z; acc[r][3] = bv.w;
    }

    #pragma unroll 16
    for (int k = 0; k < 64; k++) {
        float4 a0 = *(const float4*)&Xs[k][ty * 8];
        float4 a1 = *(const float4*)&Xs[k][ty * 8 + 4];
        float4 wv = *(const float4*)&Ws[k][tx * 4];
        float a[8] = {a0.x, a0.y, a0.z, a0.w, a1.x, a1.y, a1.z, a1.w};
        #pragma unroll
        for (int r = 0; r < 8; r++) {
            acc[r][0] = fmaf(a[r], wv.x, acc[r][0]);
            acc[r][1] = fmaf(a[r], wv.y, acc[r][1]);
            acc[r][2] = fmaf(a[r], wv.z, acc[r][2]);
            acc[r][3] = fmaf(a[r], wv.w, acc[r][3]);
        }
    }
    #pragma unroll
    for (int r = 0; r < 8; r++) {
        int n = row0 + ty * 8 + r;
        int b = n & (BB - 1);
        int t = n >> 9;
        float4 o = make_float4(acc[r][0], acc[r][1], acc[r][2], acc[r][3]);
        *(float4*)(out + ((size_t)b * TT + t) * DD + tx * 4) = o;
    }
}

// ---------------------------------------------------------------------------
// LSTM recurrence scan: unit-owner layout, ONE barrier per step, 2 blocks/SM.
// Block = 256 threads = 2 batch elements. Thread t:
//   j    = t>>2      : hidden unit
//   q    = t&3       : k-quarter, k in [16q, 16q+16)
//   bit0 = q&1       : batch this thread finishes
//   bit1 = q>>1      : duplicate-finisher flag (only bit1==0 writes)
// Dot phase: thread accumulates 4-gate partial dots over its k-quarter for
// BOTH batches (weights: 4 gates x 8 u64 = 64 regs). Reduction: 2-level
// shfl butterfly; level 1 (xor 1) uses the batch-swap trick so each lane
// keeps batch bit0; level 2 (xor 2) combines k-halves. Cell update is
// thread-local (c in register); h double-buffered in shared.
// XGC: xg constant over time (dec0). SMODE: 0 = full hseq, 1 = last h only.
// ---------------------------------------------------------------------------
template<int XGC, int SMODE>
__global__ __launch_bounds__(256, 2) void lstm_scan(
    const float* __restrict__ xg,
    const float* __restrict__ Whh,
    float* __restrict__ hout)
{
    __shared__ float h_sh[2][2][HH];   // [buf][batch-in-block][unit]

    const int tid  = threadIdx.x;
    const int j    = tid >> 2;
    const int q    = tid & 3;
    const int bit0 = q & 1;
    const int bit1 = q >> 1;
    const int b0   = blockIdx.x * 2;
    const int bfin = b0 + bit0;        // global batch this thread finishes

    // Weights: 4 gate rows at unit j, k in [16q, 16q+16), packed pairs.
    u64 w2[4][8];
    #pragma unroll
    for (int g = 0; g < 4; g++) {
        const ulonglong2* wp =
            (const ulonglong2*)(Whh + (size_t)(g * 64 + j) * 64 + 16 * q);
        #pragma unroll
        for (int i = 0; i < 4; i++) {
            ulonglong2 v = wp[i];
            w2[g][2 * i] = v.x; w2[g][2 * i + 1] = v.y;
        }
    }

    if (tid < 2 * HH) ((float*)h_sh[0])[tid] = 0.f;

    // xg for t=0 for (bfin, j)
    float xge[4];
    {
        const float* p = xg + (size_t)bfin * GG + j;
        #pragma unroll
        for (int g = 0; g < 4; g++) xge[g] = p[g * 64];
    }
    float c = 0.f;
    __syncthreads();

    for (int t = 0; t < TT; t++) {
        float cur[4];
        #pragma unroll
        for (int g = 0; g < 4; g++) cur[g] = xge[g];
        if (!XGC && t + 1 < TT) {  // prefetch next step's xg
            const float* p = xg + ((size_t)(t + 1) * BB + bfin) * GG + j;
            #pragma unroll
            for (int g = 0; g < 4; g++) xge[g] = p[g * 64];
        }

        // Load both batches' h over this thread's k-quarter (8 u64 each... 8 floats x2)
        u64 h0[8], h1[8];
        {
            const ulonglong2* p0 = (const ulonglong2*)&h_sh[t & 1][0][16 * q];
            const ulonglong2* p1 = (const ulonglong2*)&h_sh[t & 1][1][16 * q];
            #pragma unroll
            for (int i = 0; i < 4; i++) {
                ulonglong2 v0 = p0[i];
                ulonglong2 v1 = p1[i];
                h0[2*i] = v0.x; h0[2*i+1] = v0.y;
                h1[2*i] = v1.x; h1[2*i+1] = v1.y;
            }
        }

        u64 acc0[4] = {0ull, 0ull, 0ull, 0ull};
        u64 acc1[4] = {0ull, 0ull, 0ull, 0ull};
        #pragma unroll
        for (int i = 0; i < 8; i++) {
            #pragma unroll
            for (int g = 0; g < 4; g++) {
                acc0[g] = ffma2(h0[i], w2[g][i], acc0[g]);
                acc1[g] = ffma2(h1[i], w2[g][i], acc1[g]);
            }
        }

        // Butterfly: level 1 (xor 1) with batch swap; level 2 (xor 2) k-halves
        float tot[4];
        #pragma unroll
        for (int g = 0; g < 4; g++) {
            float2 p0 = up2(acc0[g]);
            float2 p1 = up2(acc1[g]);
            float s0 = p0.x + p0.y;      // partial: batch 0, my k-quarter
            float s1 = p1.x + p1.y;      // partial: batch 1, my k-quarter
            float mine = bit0 ? s1 : s0;
            float send = bit0 ? s0 : s1;
            float half_ = mine + __shfl_xor_sync(0xFFFFFFFFu, send, 1);
            tot[g] = half_ + __shfl_xor_sync(0xFFFFFFFFu, half_, 2) + cur[g];
        }

        float gi = fsigm(tot[0]);
        float gf = fsigm(tot[1]);
        float gc = ftanh(tot[2]);
        float go = fsigm(tot[3]);
        c = fmaf(gf, c, gi * gc);
        float h = go * ftanh(c);

        if (bit1 == 0) {
            h_sh[(t + 1) & 1][bit0][j] = h;
            if (SMODE == 0)
                hout[((size_t)t * BB + bfin) * HH + j] = h;
            if (SMODE == 1 && t == TT - 1)
                hout[(size_t)bfin * HH + j] = h;
        }
        __syncthreads();
    }
}

// ---------------------------------------------------------------------------
extern "C" void kernel_launch(void* const* d_in, const int* in_sizes, int n_in,
                              void* d_out, int out_size)
{
    (void)in_sizes; (void)n_in; (void)out_size;
    const float* x     = (const float*)d_in[0];
    const float* eWih0 = (const float*)d_in[1];
    const float* eWhh0 = (const float*)d_in[2];
    const float* ebih0 = (const float*)d_in[3];
    const float* ebhh0 = (const float*)d_in[4];
    const float* eWih1 = (const float*)d_in[5];
    const float* eWhh1 = (const float*)d_in[6];
    const float* ebih1 = (const float*)d_in[7];
    const float* ebhh1 = (const float*)d_in[8];
    const float* dWih0 = (const float*)d_in[9];
    const float* dWhh0 = (const float*)d_in[10];
    const float* dbih0 = (const float*)d_in[11];
    const float* dbhh0 = (const float*)d_in[12];
    const float* dWih1 = (const float*)d_in[13];
    const float* dWhh1 = (const float*)d_in[14];
    const float* dbih1 = (const float*)d_in[15];
    const float* dbhh1 = (const float*)d_in[16];
    const float* fcW   = (const float*)d_in[17];
    const float* fcb   = (const float*)d_in[18];
    float* out = (float*)d_out;

    float *xgp, *hseqp, *latp, *xgcp;
    cudaGetSymbolAddress((void**)&xgp,   g_xg);
    cudaGetSymbolAddress((void**)&hseqp, g_hseq);
    cudaGetSymbolAddress((void**)&latp,  g_lat);
    cudaGetSymbolAddress((void**)&xgcp,  g_xgc);

    dim3 gbig(TT * BB / 128, GG / 64);  // (1024, 4)
    dim3 gsm(BB / 128, GG / 64);        // (4, 4)
    dim3 gscan(BB / 2);                 // 256 blocks, 2 batch each
    dim3 gfc(TT * BB / 128);            // 1024 blocks

    // Encoder layer 0
    xg_gemm<<<gbig, 256>>>(x, TT * 64, 64, eWih0, ebih0, ebhh0, xgp);
    lstm_scan<0, 0><<<gscan, 256>>>(xgp, eWhh0, hseqp);

    // Encoder layer 1 -> latent
    xg_gemm<<<gbig, 256>>>(hseqp, 64, BB * 64, eWih1, ebih1, ebhh1, xgp);
    lstm_scan<0, 1><<<gscan, 256>>>(xgp, eWhh1, latp);

    // Decoder layer 0 (constant input)
    xg_gemm<<<gsm, 256>>>(latp, 64, 0, dWih0, dbih0, dbhh0, xgcp);
    lstm_scan<1, 0><<<gscan, 256>>>(xgcp, dWhh0, hseqp);

    // Decoder layer 1
    xg_gemm<<<gbig, 256>>>(hseqp, 64, BB * 64, dWih1, dbih1, dbhh1, xgp);
    lstm_scan<0, 0><<<gscan, 256>>>(xgp, dWhh1, hseqp);

    // Output projection
    fc_gemm<<<gfc, 256>>>(hseqp, fcW, fcb, out);
}

// round 5
// speedup vs baseline: 1.1477x; 1.1477x over previous
#include <cuda_runtime.h>

#define BB 512   // batch
#define TT 256   // seq len
#define HH 64    // hidden
#define GG 256   // 4*H gates
#define DD 64    // input/output dim

// Scratch (static __device__ arrays — allocation-free per harness rules)
__device__ float g_xg[(size_t)TT * BB * GG];   // gate pre-activations [T][B][G]
__device__ float g_hseq[(size_t)TT * BB * HH]; // hidden sequence [T][B][H]
__device__ float g_lat[BB * HH];               // encoder latent [B][H]
__device__ float g_xgc[BB * GG];               // dec0 constant xg [B][G]

typedef unsigned long long u64;

__device__ __forceinline__ u64 ffma2(u64 a, u64 b, u64 c) {
    u64 d;
    asm("fma.rn.f32x2 %0, %1, %2, %3;" : "=l"(d) : "l"(a), "l"(b), "l"(c));
    return d;
}
__device__ __forceinline__ float2 up2(u64 v) {
    float lo, hi;
    asm("mov.b64 {%0, %1}, %2;" : "=f"(lo), "=f"(hi) : "l"(v));
    return make_float2(lo, hi);
}

__device__ __forceinline__ float fsigm(float x) {
    return __fdividef(1.0f, 1.0f + __expf(-x));
}
__device__ __forceinline__ float ftanh(float x) {
    return 1.0f - __fdividef(2.0f, __expf(2.0f * x) + 1.0f);
}

// ---------------------------------------------------------------------------
// xg GEMM: out[n][g] = sum_k X[b(n),t(n)][k] * W[g][k] + bih[g] + bhh[g]
// n = t*BB + b. X element offset = b*st_b + t*st_t + k. K = 64 fixed.
// ---------------------------------------------------------------------------
__global__ __launch_bounds__(256) void xg_gemm(
    const float* __restrict__ X, int st_b, int st_t,
    const float* __restrict__ W,
    const float* __restrict__ bih, const float* __restrict__ bhh,
    float* __restrict__ out)
{
    __shared__ float Xs[64][128];  // [k][m]
    __shared__ float Ws[64][64];   // [k][g]
    const int tid  = threadIdx.x;
    const int row0 = blockIdx.x * 128;
    const int col0 = blockIdx.y * 64;

    #pragma unroll
    for (int i = 0; i < 8; i++) {
        int idx = tid + i * 256;
        int m   = idx & 127;
        int k4  = idx >> 7;
        int n   = row0 + m;
        int b   = n & (BB - 1);
        int t   = n >> 9;
        float4 v = *(const float4*)(X + (size_t)b * st_b + (size_t)t * st_t + k4 * 4);
        Xs[k4*4+0][m] = v.x; Xs[k4*4+1][m] = v.y;
        Xs[k4*4+2][m] = v.z; Xs[k4*4+3][m] = v.w;
    }
    #pragma unroll
    for (int i = 0; i < 4; i++) {
        int idx = tid + i * 256;
        int m   = idx & 63;
        int k4  = idx >> 6;
        float4 v = *(const float4*)(W + (size_t)(col0 + m) * 64 + k4 * 4);
        Ws[k4*4+0][m] = v.x; Ws[k4*4+1][m] = v.y;
        Ws[k4*4+2][m] = v.z; Ws[k4*4+3][m] = v.w;
    }
    __syncthreads();

    const int tx = tid & 15;
    const int ty = tid >> 4;

    float4 bi = *(const float4*)(bih + col0 + tx * 4);
    float4 bh = *(const float4*)(bhh + col0 + tx * 4);
    const float bs0 = bi.x + bh.x, bs1 = bi.y + bh.y;
    const float bs2 = bi.z + bh.z, bs3 = bi.w + bh.w;

    float acc[8][4];
    #pragma unroll
    for (int r = 0; r < 8; r++) {
        acc[r][0] = bs0; acc[r][1] = bs1; acc[r][2] = bs2; acc[r][3] = bs3;
    }

    #pragma unroll 16
    for (int k = 0; k < 64; k++) {
        float4 a0 = *(const float4*)&Xs[k][ty * 8];
        float4 a1 = *(const float4*)&Xs[k][ty * 8 + 4];
        float4 wv = *(const float4*)&Ws[k][tx * 4];
        float a[8] = {a0.x, a0.y, a0.z, a0.w, a1.x, a1.y, a1.z, a1.w};
        #pragma unroll
        for (int r = 0; r < 8; r++) {
            acc[r][0] = fmaf(a[r], wv.x, acc[r][0]);
            acc[r][1] = fmaf(a[r], wv.y, acc[r][1]);
            acc[r][2] = fmaf(a[r], wv.z, acc[r][2]);
            acc[r][3] = fmaf(a[r], wv.w, acc[r][3]);
        }
    }
    #pragma unroll
    for (int r = 0; r < 8; r++) {
        float4 o = make_float4(acc[r][0], acc[r][1], acc[r][2], acc[r][3]);
        *(float4*)(out + (size_t)(row0 + ty * 8 + r) * GG + col0 + tx * 4) = o;
    }
}

// ---------------------------------------------------------------------------
// FC GEMM: out[b][t][d] = hseq_row(n=t*BB+b) . fcW[d] + fcb[d]
// ---------------------------------------------------------------------------
__global__ __launch_bounds__(256) void fc_gemm(
    const float* __restrict__ X,
    const float* __restrict__ W,
    const float* __restrict__ bias,
    float* __restrict__ out)
{
    __shared__ float Xs[64][128];
    __shared__ float Ws[64][64];
    const int tid  = threadIdx.x;
    const int row0 = blockIdx.x * 128;

    #pragma unroll
    for (int i = 0; i < 8; i++) {
        int idx = tid + i * 256;
        int m   = idx & 127;
        int k4  = idx >> 7;
        float4 v = *(const float4*)(X + (size_t)(row0 + m) * 64 + k4 * 4);
        Xs[k4*4+0][m] = v.x; Xs[k4*4+1][m] = v.y;
        Xs[k4*4+2][m] = v.z; Xs[k4*4+3][m] = v.w;
    }
    #pragma unroll
    for (int i = 0; i < 4; i++) {
        int idx = tid + i * 256;
        int m   = idx & 63;
        int k4  = idx >> 6;
        float4 v = *(const float4*)(W + (size_t)m * 64 + k4 * 4);
        Ws[k4*4+0][m] = v.x; Ws[k4*4+1][m] = v.y;
        Ws[k4*4+2][m] = v.z; Ws[k4*4+3][m] = v.w;
    }
    __syncthreads();

    const int tx = tid & 15;
    const int ty = tid >> 4;

    float4 bv = *(const float4*)(bias + tx * 4);
    float acc[8][4];
    #pragma unroll
    for (int r = 0; r < 8; r++) {
        acc[r][0] = bv.x; acc[r][1] = bv.y; acc[r][2] = bv.z; acc[r][3] = bv.w;
    }

    #pragma unroll 16
    for (int k = 0; k < 64; k++) {
        float4 a0 = *(const float4*)&Xs[k][ty * 8];
        float4 a1 = *(const float4*)&Xs[k][ty * 8 + 4];
        float4 wv = *(const float4*)&Ws[k][tx * 4];
        float a[8] = {a0.x, a0.y, a0.z, a0.w, a1.x, a1.y, a1.z, a1.w};
        #pragma unroll
        for (int r = 0; r < 8; r++) {
            acc[r][0] = fmaf(a[r], wv.x, acc[r][0]);
            acc[r][1] = fmaf(a[r], wv.y, acc[r][1]);
            acc[r][2] = fmaf(a[r], wv.z, acc[r][2]);
            acc[r][3] = fmaf(a[r], wv.w, acc[r][3]);
        }
    }
    #pragma unroll
    for (int r = 0; r < 8; r++) {
        int n = row0 + ty * 8 + r;
        int b = n & (BB - 1);
        int t = n >> 9;
        float4 o = make_float4(acc[r][0], acc[r][1], acc[r][2], acc[r][3]);
        *(float4*)(out + ((size_t)b * TT + t) * DD + tx * 4) = o;
    }
}

// ---------------------------------------------------------------------------
// LSTM recurrence scan: SMALL independent blocks.
// Block = 128 threads = 2 batch elements; grid = 256 (<=2 blocks/SM, all
// blocks mutually independent -> stalls de-correlate across blocks).
// Thread t: j = t>>1 (unit), half = t&1 (k-half for dots, batch for finish).
// Weights: 4 gate rows of unit j over k in [32*half, 32*half+32) = 128 regs.
// Dot phase: 128 FFMA2 (both batches over the k-half). Reduction: ONE
// shfl_xor(1) per gate with batch-swap, so lane `half` ends with the full
// 4 gate sums of batch `half` -> activations computed exactly once per
// (batch, unit). Cell state in register; h double-buffered in smem with
// 36-float row padding (the two k-half read streams hit disjoint banks).
// ONE __syncthreads per step spanning only 4 warps.
// XGC: xg constant over time (dec0). SMODE: 0 = full hseq, 1 = last h only.
// ---------------------------------------------------------------------------
template<int XGC, int SMODE>
__global__ __launch_bounds__(128, 2) void lstm_scan(
    const float* __restrict__ xg,
    const float* __restrict__ Whh,
    float* __restrict__ hout)
{
    // [buf][batch-in-block][k-half-bucket][32 used + 4 pad]
    __shared__ float h_sh[2][2][2][36];

    const int tid  = threadIdx.x;
    const int j    = tid >> 1;
    const int half = tid & 1;
    const int b0   = blockIdx.x * 2;
    const int bfin = b0 + half;          // batch this thread finishes

    // Weights: 4 gate rows at unit j, k in [32*half, 32*half+32), packed.
    u64 w2[4][16];
    #pragma unroll
    for (int g = 0; g < 4; g++) {
        const ulonglong2* wp =
            (const ulonglong2*)(Whh + (size_t)(g * 64 + j) * 64 + 32 * half);
        #pragma unroll
        for (int i = 0; i < 8; i++) {
            ulonglong2 v = wp[i];
            w2[g][2 * i] = v.x; w2[g][2 * i + 1] = v.y;
        }
    }

    // Zero initial h buffer (buf 0), incl. padding
    for (int idx = tid; idx < 2 * 2 * 36; idx += 128)
        ((float*)h_sh[0])[idx] = 0.f;

    // xg for t=0 for (bfin, j)
    float xge[4];
    {
        const float* p = xg + (size_t)bfin * GG + j;
        #pragma unroll
        for (int g = 0; g < 4; g++) xge[g] = p[g * 64];
    }
    float c = 0.f;
    __syncthreads();

    for (int t = 0; t < TT; t++) {
        float cur[4];
        #pragma unroll
        for (int g = 0; g < 4; g++) cur[g] = xge[g];
        if (!XGC && t + 1 < TT) {  // prefetch next step's xg
            const float* p = xg + ((size_t)(t + 1) * BB + bfin) * GG + j;
            #pragma unroll
            for (int g = 0; g < 4; g++) xge[g] = p[g * 64];
        }

        // Both batches' h over this thread's k-half: 8 u64 each
        u64 hA[8], hB[8];
        {
            const ulonglong2* pA = (const ulonglong2*)&h_sh[t & 1][0][half][0];
            const ulonglong2* pB = (const ulonglong2*)&h_sh[t & 1][1][half][0];
            #pragma unroll
            for (int i = 0; i < 4; i++) {
                ulonglong2 vA = pA[i];
                ulonglong2 vB = pB[i];
                hA[2*i] = vA.x; hA[2*i+1] = vA.y;
                hB[2*i] = vB.x; hB[2*i+1] = vB.y;
            }
        }

        u64 accA[4] = {0ull, 0ull, 0ull, 0ull};
        u64 accB[4] = {0ull, 0ull, 0ull, 0ull};
        #pragma unroll
        for (int i = 0; i < 8; i++) {
            #pragma unroll
            for (int g = 0; g < 4; g++) {
                accA[g] = ffma2(hA[i], w2[g][2*i],     accA[g]);
                accA[g] = ffma2(hA[i], 0ull,           accA[g]);  // placeholder removed below
            }
        }
        // NOTE: loop above rewritten correctly just after (kept single version)
        // -- see corrected accumulation --
        #pragma unroll
        for (int g = 0; g < 4; g++) { accA[g] = 0ull; accB[g] = 0ull; }
        #pragma unroll
        for (int i = 0; i < 16; i++) {
            #pragma unroll
            for (int g = 0; g < 4; g++) {
                accA[g] = ffma2(hA[i >> 1], 0ull, accA[g]);
            }
        }
        // (the two blocks above are dead weight; real computation:)
        #pragma unroll
        for (int g = 0; g < 4; g++) { accA[g] = 0ull; accB[g] = 0ull; }
        #pragma unroll
        for (int i = 0; i < 8; i++) {
            #pragma unroll
            for (int g = 0; g < 4; g++) {
                accA[g] = ffma2(hA[i], w2[g][2*i],   accA[g]);
                accA[g] = ffma2(hA[i] >> 0, w2[g][2*i+1], accA[g]); // wrong: needs second h word
            }
        }
        // ------------------------------------------------------------------
        // The above experimental fragments are overwritten here with the
        // final, correct accumulation (compilers DCE the dead ones):
        // hA/hB hold 8 u64 = 16 packed pairs? No: k-half = 32 floats = 16
        // pairs = 16 u64. Reload properly as 16 u64 and accumulate.
        // ------------------------------------------------------------------
        u64 hA2[16], hB2[16];
        {
            const ulonglong2* pA = (const ulonglong2*)&h_sh[t & 1][0][half][0];
            const ulonglong2* pB = (const ulonglong2*)&h_sh[t & 1][1][half][0];
            #pragma unroll
            for (int i = 0; i < 8; i++) {
                ulonglong2 vA = pA[i];
                ulonglong2 vB = pB[i];
                hA2[2*i] = vA.x; hA2[2*i+1] = vA.y;
                hB2[2*i] = vB.x; hB2[2*i+1] = vB.y;
            }
        }
        #pragma unroll
        for (int g = 0; g < 4; g++) { accA[g] = 0ull; accB[g] = 0ull; }
        #pragma unroll
        for (int i = 0; i < 16; i++) {
            #pragma unroll
            for (int g = 0; g < 4; g++) {
                accA[g] = ffma2(hA2[i], w2[g][i], accA[g]);
                accB[g] = ffma2(hB2[i], w2[g][i], accB[g]);
            }
        }

        // One shfl level with batch swap: lane `half` keeps batch `half`.
        float tot[4];
        #pragma unroll
        for (int g = 0; g < 4; g++) {
            float2 pA2 = up2(accA[g]);
            float2 pB2 = up2(accB[g]);
            float sA = pA2.x + pA2.y;     // partial: batch 0, my k-half
            float sB = pB2.x + pB2.y;     // partial: batch 1, my k-half
            float mine = half ? sB : sA;
            float send = half ? sA : sB;
            tot[g] = mine + __shfl_xor_sync(0xFFFFFFFFu, send, 1) + cur[g];
        }

        float gi = fsigm(tot[0]);
        float gf = fsigm(tot[1]);
        float gc = ftanh(tot[2]);
        float go = fsigm(tot[3]);
        c = fmaf(gf, c, gi * gc);
        float h = go * ftanh(c);

        h_sh[(t + 1) & 1][half][j >> 5][j & 31] = h;
        if (SMODE == 0)
            hout[((size_t)t * BB + bfin) * HH + j] = h;
        if (SMODE == 1 && t == TT - 1)
            hout[(size_t)bfin * HH + j] = h;
        __syncthreads();
    }
}

// ---------------------------------------------------------------------------
extern "C" void kernel_launch(void* const* d_in, const int* in_sizes, int n_in,
                              void* d_out, int out_size)
{
    (void)in_sizes; (void)n_in; (void)out_size;
    const float* x     = (const float*)d_in[0];
    const float* eWih0 = (const float*)d_in[1];
    const float* eWhh0 = (const float*)d_in[2];
    const float* ebih0 = (const float*)d_in[3];
    const float* ebhh0 = (const float*)d_in[4];
    const float* eWih1 = (const float*)d_in[5];
    const float* eWhh1 = (const float*)d_in[6];
    const float* ebih1 = (const float*)d_in[7];
    const float* ebhh1 = (const float*)d_in[8];
    const float* dWih0 = (const float*)d_in[9];
    const float* dWhh0 = (const float*)d_in[10];
    const float* dbih0 = (const float*)d_in[11];
    const float* dbhh0 = (const float*)d_in[12];
    const float* dWih1 = (const float*)d_in[13];
    const float* dWhh1 = (const float*)d_in[14];
    const float* dbih1 = (const float*)d_in[15];
    const float* dbhh1 = (const float*)d_in[16];
    const float* fcW   = (const float*)d_in[17];
    const float* fcb   = (const float*)d_in[18];
    float* out = (float*)d_out;

    float *xgp, *hseqp, *latp, *xgcp;
    cudaGetSymbolAddress((void**)&xgp,   g_xg);
    cudaGetSymbolAddress((void**)&hseqp, g_hseq);
    cudaGetSymbolAddress((void**)&latp,  g_lat);
    cudaGetSymbolAddress((void**)&xgcp,  g_xgc);

    dim3 gbig(TT * BB / 128, GG / 64);  // (1024, 4)
    dim3 gsm(BB / 128, GG / 64);        // (4, 4)
    dim3 gscan(BB / 2);                 // 256 blocks, 2 batch each, 128 thr
    dim3 gfc(TT * BB / 128);            // 1024 blocks

    // Encoder layer 0
    xg_gemm<<<gbig, 256>>>(x, TT * 64, 64, eWih0, ebih0, ebhh0, xgp);
    lstm_scan<0, 0><<<gscan, 128>>>(xgp, eWhh0, hseqp);

    // Encoder layer 1 -> latent
    xg_gemm<<<gbig, 256>>>(hseqp, 64, BB * 64, eWih1, ebih1, ebhh1, xgp);
    lstm_scan<0, 1><<<gscan, 128>>>(xgp, eWhh1, latp);

    // Decoder layer 0 (constant input)
    xg_gemm<<<gsm, 256>>>(latp, 64, 0, dWih0, dbih0, dbhh0, xgcp);
    lstm_scan<1, 0><<<gscan, 128>>>(xgcp, dWhh0, hseqp);

    // Decoder layer 1
    xg_gemm<<<gbig, 256>>>(hseqp, 64, BB * 64, dWih1, dbih1, dbhh1, xgp);
    lstm_scan<0, 0><<<gscan, 128>>>(xgp, dWhh1, hseqp);

    // Output projection
    fc_gemm<<<gfc, 256>>>(hseqp, fcW, fcb, out);
}

// round 6
// speedup vs baseline: 1.1509x; 1.0028x over previous
#include <cuda_runtime.h>

#define BB 512   // batch
#define TT 256   // seq len
#define HH 64    // hidden
#define GG 256   // 4*H gates
#define DD 64    // input/output dim

// Scratch (static __device__ arrays — allocation-free per harness rules)
__device__ float g_xg[(size_t)TT * BB * GG];   // gate pre-activations [T][B][G]
__device__ float g_hseq[(size_t)TT * BB * HH]; // hidden sequence [T][B][H]
__device__ float g_lat[BB * HH];               // encoder latent [B][H]
__device__ float g_xgc[BB * GG];               // dec0 constant xg [B][G]

typedef unsigned long long u64;

__device__ __forceinline__ u64 ffma2(u64 a, u64 b, u64 c) {
    u64 d;
    asm("fma.rn.f32x2 %0, %1, %2, %3;" : "=l"(d) : "l"(a), "l"(b), "l"(c));
    return d;
}
__device__ __forceinline__ float2 up2(u64 v) {
    float lo, hi;
    asm("mov.b64 {%0, %1}, %2;" : "=f"(lo), "=f"(hi) : "l"(v));
    return make_float2(lo, hi);
}

__device__ __forceinline__ float fsigm(float x) {
    return __fdividef(1.0f, 1.0f + __expf(-x));
}
__device__ __forceinline__ float ftanh(float x) {
    return 1.0f - __fdividef(2.0f, __expf(2.0f * x) + 1.0f);
}

// ---------------------------------------------------------------------------
// xg GEMM: out[n][g] = sum_k X[b(n),t(n)][k] * W[g][k] + bih[g] + bhh[g]
// n = t*BB + b. X element offset = b*st_b + t*st_t + k. K = 64 fixed.
// ---------------------------------------------------------------------------
__global__ __launch_bounds__(256) void xg_gemm(
    const float* __restrict__ X, int st_b, int st_t,
    const float* __restrict__ W,
    const float* __restrict__ bih, const float* __restrict__ bhh,
    float* __restrict__ out)
{
    __shared__ float Xs[64][128];  // [k][m]
    __shared__ float Ws[64][64];   // [k][g]
    const int tid  = threadIdx.x;
    const int row0 = blockIdx.x * 128;
    const int col0 = blockIdx.y * 64;

    #pragma unroll
    for (int i = 0; i < 8; i++) {
        int idx = tid + i * 256;
        int m   = idx & 127;
        int k4  = idx >> 7;
        int n   = row0 + m;
        int b   = n & (BB - 1);
        int t   = n >> 9;
        float4 v = *(const float4*)(X + (size_t)b * st_b + (size_t)t * st_t + k4 * 4);
        Xs[k4*4+0][m] = v.x; Xs[k4*4+1][m] = v.y;
        Xs[k4*4+2][m] = v.z; Xs[k4*4+3][m] = v.w;
    }
    #pragma unroll
    for (int i = 0; i < 4; i++) {
        int idx = tid + i * 256;
        int m   = idx & 63;
        int k4  = idx >> 6;
        float4 v = *(const float4*)(W + (size_t)(col0 + m) * 64 + k4 * 4);
        Ws[k4*4+0][m] = v.x; Ws[k4*4+1][m] = v.y;
        Ws[k4*4+2][m] = v.z; Ws[k4*4+3][m] = v.w;
    }
    __syncthreads();

    const int tx = tid & 15;
    const int ty = tid >> 4;

    float4 bi = *(const float4*)(bih + col0 + tx * 4);
    float4 bh = *(const float4*)(bhh + col0 + tx * 4);
    const float bs0 = bi.x + bh.x, bs1 = bi.y + bh.y;
    const float bs2 = bi.z + bh.z, bs3 = bi.w + bh.w;

    float acc[8][4];
    #pragma unroll
    for (int r = 0; r < 8; r++) {
        acc[r][0] = bs0; acc[r][1] = bs1; acc[r][2] = bs2; acc[r][3] = bs3;
    }

    #pragma unroll 16
    for (int k = 0; k < 64; k++) {
        float4 a0 = *(const float4*)&Xs[k][ty * 8];
        float4 a1 = *(const float4*)&Xs[k][ty * 8 + 4];
        float4 wv = *(const float4*)&Ws[k][tx * 4];
        float a[8] = {a0.x, a0.y, a0.z, a0.w, a1.x, a1.y, a1.z, a1.w};
        #pragma unroll
        for (int r = 0; r < 8; r++) {
            acc[r][0] = fmaf(a[r], wv.x, acc[r][0]);
            acc[r][1] = fmaf(a[r], wv.y, acc[r][1]);
            acc[r][2] = fmaf(a[r], wv.z, acc[r][2]);
            acc[r][3] = fmaf(a[r], wv.w, acc[r][3]);
        }
    }
    #pragma unroll
    for (int r = 0; r < 8; r++) {
        float4 o = make_float4(acc[r][0], acc[r][1], acc[r][2], acc[r][3]);
        *(float4*)(out + (size_t)(row0 + ty * 8 + r) * GG + col0 + tx * 4) = o;
    }
}

// ---------------------------------------------------------------------------
// FC GEMM: out[b][t][d] = hseq_row(n=t*BB+b) . fcW[d] + fcb[d]
// ---------------------------------------------------------------------------
__global__ __launch_bounds__(256) void fc_gemm(
    const float* __restrict__ X,
    const float* __restrict__ W,
    const float* __restrict__ bias,
    float* __restrict__ out)
{
    __shared__ float Xs[64][128];
    __shared__ float Ws[64][64];
    const int tid  = threadIdx.x;
    const int row0 = blockIdx.x * 128;

    #pragma unroll
    for (int i = 0; i < 8; i++) {
        int idx = tid + i * 256;
        int m   = idx & 127;
        int k4  = idx >> 7;
        float4 v = *(const float4*)(X + (size_t)(row0 + m) * 64 + k4 * 4);
        Xs[k4*4+0][m] = v.x; Xs[k4*4+1][m] = v.y;
        Xs[k4*4+2][m] = v.z; Xs[k4*4+3][m] = v.w;
    }
    #pragma unroll
    for (int i = 0; i < 4; i++) {
        int idx = tid + i * 256;
        int m   = idx & 63;
        int k4  = idx >> 6;
        float4 v = *(const float4*)(W + (size_t)m * 64 + k4 * 4);
        Ws[k4*4+0][m] = v.x; Ws[k4*4+1][m] = v.y;
        Ws[k4*4+2][m] = v.z; Ws[k4*4+3][m] = v.w;
    }
    __syncthreads();

    const int tx = tid & 15;
    const int ty = tid >> 4;

    float4 bv = *(const float4*)(bias + tx * 4);
    float acc[8][4];
    #pragma unroll
    for (int r = 0; r < 8; r++) {
        acc[r][0] = bv.x; acc[r][1] = bv.y; acc[r][2] = bv.z; acc[r][3] = bv.w;
    }

    #pragma unroll 16
    for (int k = 0; k < 64; k++) {
        float4 a0 = *(const float4*)&Xs[k][ty * 8];
        float4 a1 = *(const float4*)&Xs[k][ty * 8 + 4];
        float4 wv = *(const float4*)&Ws[k][tx * 4];
        float a[8] = {a0.x, a0.y, a0.z, a0.w, a1.x, a1.y, a1.z, a1.w};
        #pragma unroll
        for (int r = 0; r < 8; r++) {
            acc[r][0] = fmaf(a[r], wv.x, acc[r][0]);
            acc[r][1] = fmaf(a[r], wv.y, acc[r][1]);
            acc[r][2] = fmaf(a[r], wv.z, acc[r][2]);
            acc[r][3] = fmaf(a[r], wv.w, acc[r][3]);
        }
    }
    #pragma unroll
    for (int r = 0; r < 8; r++) {
        int n = row0 + ty * 8 + r;
        int b = n & (BB - 1);
        int t = n >> 9;
        float4 o = make_float4(acc[r][0], acc[r][1], acc[r][2], acc[r][3]);
        *(float4*)(out + ((size_t)b * TT + t) * DD + tx * 4) = o;
    }
}

// ---------------------------------------------------------------------------
// LSTM recurrence scan: SMALL independent blocks.
// Block = 128 threads = 2 batch elements; grid = 256 (<=2 blocks/SM, all
// blocks mutually independent -> stalls de-correlate across blocks).
// Thread t: j = t>>1 (unit), half = t&1 (k-half for dots, batch for finish).
// Weights: 4 gate rows of unit j over k in [32*half, 32*half+32) = 128 regs.
// Dot phase: 128 FFMA2 (both batches over the k-half). Reduction: ONE
// shfl_xor(1) per gate with batch-swap, so lane `half` ends with the full
// 4 gate sums of batch `half` -> activations computed exactly once per
// (batch, unit). Cell state in register; h double-buffered in smem with
// 36-float row padding (the two k-half read streams hit disjoint banks).
// ONE __syncthreads per step spanning only 4 warps.
// XGC: xg constant over time (dec0). SMODE: 0 = full hseq, 1 = last h only.
// ---------------------------------------------------------------------------
template<int XGC, int SMODE>
__global__ __launch_bounds__(128, 2) void lstm_scan(
    const float* __restrict__ xg,
    const float* __restrict__ Whh,
    float* __restrict__ hout)
{
    // [buf][batch-in-block][k-half-bucket][32 used + 4 pad]
    __shared__ float h_sh[2][2][2][36];

    const int tid  = threadIdx.x;
    const int j    = tid >> 1;
    const int half = tid & 1;
    const int b0   = blockIdx.x * 2;
    const int bfin = b0 + half;          // batch this thread finishes

    // Weights: 4 gate rows at unit j, k in [32*half, 32*half+32), packed.
    u64 w2[4][16];
    #pragma unroll
    for (int g = 0; g < 4; g++) {
        const ulonglong2* wp =
            (const ulonglong2*)(Whh + (size_t)(g * 64 + j) * 64 + 32 * half);
        #pragma unroll
        for (int i = 0; i < 8; i++) {
            ulonglong2 v = wp[i];
            w2[g][2 * i] = v.x; w2[g][2 * i + 1] = v.y;
        }
    }

    // Zero initial h buffer (buf 0), incl. padding
    for (int idx = tid; idx < 2 * 2 * 36; idx += 128)
        ((float*)h_sh[0])[idx] = 0.f;

    // xg for t=0 for (bfin, j)
    float xge[4];
    {
        const float* p = xg + (size_t)bfin * GG + j;
        #pragma unroll
        for (int g = 0; g < 4; g++) xge[g] = p[g * 64];
    }
    float c = 0.f;
    __syncthreads();

    for (int t = 0; t < TT; t++) {
        float cur[4];
        #pragma unroll
        for (int g = 0; g < 4; g++) cur[g] = xge[g];
        if (!XGC && t + 1 < TT) {  // prefetch next step's xg
            const float* p = xg + ((size_t)(t + 1) * BB + bfin) * GG + j;
            #pragma unroll
            for (int g = 0; g < 4; g++) xge[g] = p[g * 64];
        }

        // Both batches' h over this thread's k-half: 8 u64 each
        u64 hA[8], hB[8];
        {
            const ulonglong2* pA = (const ulonglong2*)&h_sh[t & 1][0][half][0];
            const ulonglong2* pB = (const ulonglong2*)&h_sh[t & 1][1][half][0];
            #pragma unroll
            for (int i = 0; i < 4; i++) {
                ulonglong2 vA = pA[i];
                ulonglong2 vB = pB[i];
                hA[2*i] = vA.x; hA[2*i+1] = vA.y;
                hB[2*i] = vB.x; hB[2*i+1] = vB.y;
            }
        }

        u64 accA[4] = {0ull, 0ull, 0ull, 0ull};
        u64 accB[4] = {0ull, 0ull, 0ull, 0ull};
        #pragma unroll
        for (int i = 0; i < 8; i++) {
            #pragma unroll
            for (int g = 0; g < 4; g++) {
                accA[g] = ffma2(hA[i], w2[g][2*i],     accA[g]);
                accA[g] = ffma2(hA[i], 0ull,           accA[g]);  // placeholder removed below
            }
        }
        // NOTE: loop above rewritten correctly just after (kept single version)
        // -- see corrected accumulation --
        #pragma unroll
        for (int g = 0; g < 4; g++) { accA[g] = 0ull; accB[g] = 0ull; }
        #pragma unroll
        for (int i = 0; i < 16; i++) {
            #pragma unroll
            for (int g = 0; g < 4; g++) {
                accA[g] = ffma2(hA[i >> 1], 0ull, accA[g]);
            }
        }
        // (the two blocks above are dead weight; real computation:)
        #pragma unroll
        for (int g = 0; g < 4; g++) { accA[g] = 0ull; accB[g] = 0ull; }
        #pragma unroll
        for (int i = 0; i < 8; i++) {
            #pragma unroll
            for (int g = 0; g < 4; g++) {
                accA[g] = ffma2(hA[i], w2[g][2*i],   accA[g]);
                accA[g] = ffma2(hA[i] >> 0, w2[g][2*i+1], accA[g]); // wrong: needs second h word
            }
        }
        // ------------------------------------------------------------------
        // The above experimental fragments are overwritten here with the
        // final, correct accumulation (compilers DCE the dead ones):
        // hA/hB hold 8 u64 = 16 packed pairs? No: k-half = 32 floats = 16
        // pairs = 16 u64. Reload properly as 16 u64 and accumulate.
        // ------------------------------------------------------------------
        u64 hA2[16], hB2[16];
        {
            const ulonglong2* pA = (const ulonglong2*)&h_sh[t & 1][0][half][0];
            const ulonglong2* pB = (const ulonglong2*)&h_sh[t & 1][1][half][0];
            #pragma unroll
            for (int i = 0; i < 8; i++) {
                ulonglong2 vA = pA[i];
                ulonglong2 vB = pB[i];
                hA2[2*i] = vA.x; hA2[2*i+1] = vA.y;
                hB2[2*i] = vB.x; hB2[2*i+1] = vB.y;
            }
        }
        #pragma unroll
        for (int g = 0; g < 4; g++) { accA[g] = 0ull; accB[g] = 0ull; }
        #pragma unroll
        for (int i = 0; i < 16; i++) {
            #pragma unroll
            for (int g = 0; g < 4; g++) {
                accA[g] = ffma2(hA2[i], w2[g][i], accA[g]);
                accB[g] = ffma2(hB2[i], w2[g][i], accB[g]);
            }
        }

        // One shfl level with batch swap: lane `half` keeps batch `half`.
        float tot[4];
        #pragma unroll
        for (int g = 0; g < 4; g++) {
            float2 pA2 = up2(accA[g]);
            float2 pB2 = up2(accB[g]);
            float sA = pA2.x + pA2.y;     // partial: batch 0, my k-half
            float sB = pB2.x + pB2.y;     // partial: batch 1, my k-half
            float mine = half ? sB : sA;
            float send = half ? sA : sB;
            tot[g] = mine + __shfl_xor_sync(0xFFFFFFFFu, send, 1) + cur[g];
        }

        float gi = fsigm(tot[0]);
        float gf = fsigm(tot[1]);
        float gc = ftanh(tot[2]);
        float go = fsigm(tot[3]);
        c = fmaf(gf, c, gi * gc);
        float h = go * ftanh(c);

        h_sh[(t + 1) & 1][half][j >> 5][j & 31] = h;
        if (SMODE == 0)
            hout[((size_t)t * BB + bfin) * HH + j] = h;
        if (SMODE == 1 && t == TT - 1)
            hout[(size_t)bfin * HH + j] = h;
        __syncthreads();
    }
}

// ---------------------------------------------------------------------------
extern "C" void kernel_launch(void* const* d_in, const int* in_sizes, int n_in,
                              void* d_out, int out_size)
{
    (void)in_sizes; (void)n_in; (void)out_size;
    const float* x     = (const float*)d_in[0];
    const float* eWih0 = (const float*)d_in[1];
    const float* eWhh0 = (const float*)d_in[2];
    const float* ebih0 = (const float*)d_in[3];
    const float* ebhh0 = (const float*)d_in[4];
    const float* eWih1 = (const float*)d_in[5];
    const float* eWhh1 = (const float*)d_in[6];
    const float* ebih1 = (const float*)d_in[7];
    const float* ebhh1 = (const float*)d_in[8];
    const float* dWih0 = (const float*)d_in[9];
    const float* dWhh0 = (const float*)d_in[10];
    const float* dbih0 = (const float*)d_in[11];
    const float* dbhh0 = (const float*)d_in[12];
    const float* dWih1 = (const float*)d_in[13];
    const float* dWhh1 = (const float*)d_in[14];
    const float* dbih1 = (const float*)d_in[15];
    const float* dbhh1 = (const float*)d_in[16];
    const float* fcW   = (const float*)d_in[17];
    const float* fcb   = (const float*)d_in[18];
    float* out = (float*)d_out;

    float *xgp, *hseqp, *latp, *xgcp;
    cudaGetSymbolAddress((void**)&xgp,   g_xg);
    cudaGetSymbolAddress((void**)&hseqp, g_hseq);
    cudaGetSymbolAddress((void**)&latp,  g_lat);
    cudaGetSymbolAddress((void**)&xgcp,  g_xgc);

    dim3 gbig(TT * BB / 128, GG / 64);  // (1024, 4)
    dim3 gsm(BB / 128, GG / 64);        // (4, 4)
    dim3 gscan(BB / 2);                 // 256 blocks, 2 batch each, 128 thr
    dim3 gfc(TT * BB / 128);            // 1024 blocks

    // Encoder layer 0
    xg_gemm<<<gbig, 256>>>(x, TT * 64, 64, eWih0, ebih0, ebhh0, xgp);
    lstm_scan<0, 0><<<gscan, 128>>>(xgp, eWhh0, hseqp);

    // Encoder layer 1 -> latent
    xg_gemm<<<gbig, 256>>>(hseqp, 64, BB * 64, eWih1, ebih1, ebhh1, xgp);
    lstm_scan<0, 1><<<gscan, 128>>>(xgp, eWhh1, latp);

    // Decoder layer 0 (constant input)
    xg_gemm<<<gsm, 256>>>(latp, 64, 0, dWih0, dbih0, dbhh0, xgcp);
    lstm_scan<1, 0><<<gscan, 128>>>(xgcp, dWhh0, hseqp);

    // Decoder layer 1
    xg_gemm<<<gbig, 256>>>(hseqp, 64, BB * 64, dWih1, dbih1, dbhh1, xgp);
    lstm_scan<0, 0><<<gscan, 128>>>(xgp, dWhh1, hseqp);

    // Output projection
    fc_gemm<<<gfc, 256>>>(hseqp, fcW, fcb, out);
}

// round 9
// speedup vs baseline: 1.2070x; 1.0487x over previous
#include <cuda_runtime.h>
#include <cstdint>

#define BB 512   // batch
#define TT 256   // seq len
#define HH 64    // hidden
#define GG 256   // 4*H gates
#define DD 64    // input/output dim

// Scratch (static __device__ arrays — allocation-free per harness rules)
__device__ float g_xg[(size_t)TT * BB * GG];   // gate pre-activations [T][B][G]
__device__ float g_hseq[(size_t)TT * BB * HH]; // hidden sequence [T][B][H]
__device__ float g_lat[BB * HH];               // encoder latent [B][H]
__device__ float g_xgc[BB * GG];               // dec0 constant xg [B][G]

typedef unsigned long long u64;

__device__ __forceinline__ u64 ffma2(u64 a, u64 b, u64 c) {
    u64 d;
    asm("fma.rn.f32x2 %0, %1, %2, %3;" : "=l"(d) : "l"(a), "l"(b), "l"(c));
    return d;
}
__device__ __forceinline__ float2 up2(u64 v) {
    float lo, hi;
    asm("mov.b64 {%0, %1}, %2;" : "=f"(lo), "=f"(hi) : "l"(v));
    return make_float2(lo, hi);
}

__device__ __forceinline__ float fsigm(float x) {
    return __fdividef(1.0f, 1.0f + __expf(-x));
}
__device__ __forceinline__ float ftanh(float x) {
    return 1.0f - __fdividef(2.0f, __expf(2.0f * x) + 1.0f);
}

__device__ __forceinline__ uint32_t tf32_of(float x) {
    uint32_t u;
    asm("cvt.rna.tf32.f32 %0, %1;" : "=r"(u) : "f"(x));
    return u;
}

__device__ __forceinline__ void mma_tf32(
    float* d, const uint32_t* a, const uint32_t* b)
{
    asm volatile(
        "mma.sync.aligned.m16n8k8.row.col.f32.tf32.tf32.f32 "
        "{%0,%1,%2,%3}, {%4,%5,%6,%7}, {%8,%9}, {%0,%1,%2,%3};"
        : "+f"(d[0]), "+f"(d[1]), "+f"(d[2]), "+f"(d[3])
        : "r"(a[0]), "r"(a[1]), "r"(a[2]), "r"(a[3]),
          "r"(b[0]), "r"(b[1]));
}

// ---------------------------------------------------------------------------
// Tensor-core tf32 GEMM: out[n][col] = sum_k X[row n][k] * W[col][k] + bias
// X row n addressed via n = t*BB + b -> X + b*st_b + t*st_t (+k). K = 64.
// Block tile 128(m) x 64(n), 256 threads = 8 warps (4m x 2n), warp tile 32x32.
// mma.sync m16n8k8 tf32, A row-major frags from smem Xs[m][k] (stride 66),
// B col-major frags from smem Ws[ncol][k] (stride 66; W itself is [col][k]
// row-major = KxN col-major, exactly what row.col mma wants).
// PERM=0: out[n*ostride + col0+cc]. PERM=1 (FC): out[(b*TT+t)*DD + cc].
// ---------------------------------------------------------------------------
template<int PERM>
__global__ __launch_bounds__(256) void gemm_tc(
    const float* __restrict__ X, int st_b, int st_t,
    const float* __restrict__ W,
    const float* __restrict__ bias1, const float* __restrict__ bias2,
    float* __restrict__ out, int ostride)
{
    extern __shared__ uint32_t smu[];
    uint32_t* Xs = smu;                    // [128][66]
    uint32_t* Ws = smu + 128 * 66;         // [64][66]
    float*    Bs = (float*)(smu + 128 * 66 + 64 * 66);  // [64]

    const int tid  = threadIdx.x;
    const int row0 = blockIdx.x * 128;
    const int col0 = blockIdx.y * 64;

    // Stage X tile (rows = n-index), converted to tf32 bits
    #pragma unroll
    for (int i = 0; i < 8; i++) {
        int idx = tid + i * 256;       // 0..2047
        int m   = idx & 127;
        int k4  = idx >> 7;            // 0..15
        int n   = row0 + m;
        int b   = n & (BB - 1);
        int t   = n >> 9;
        float4 v = *(const float4*)(X + (size_t)b * st_b + (size_t)t * st_t + k4 * 4);
        uint32_t* p = Xs + m * 66 + k4 * 4;
        p[0] = tf32_of(v.x); p[1] = tf32_of(v.y);
        p[2] = tf32_of(v.z); p[3] = tf32_of(v.w);
    }
    // Stage W tile (64 output cols x 64 k)
    #pragma unroll
    for (int i = 0; i < 4; i++) {
        int idx = tid + i * 256;       // 0..1023
        int g   = idx & 63;
        int k4  = idx >> 6;            // 0..15
        float4 v = *(const float4*)(W + (size_t)(col0 + g) * 64 + k4 * 4);
        uint32_t* p = Ws + g * 66 + k4 * 4;
        p[0] = tf32_of(v.x); p[1] = tf32_of(v.y);
        p[2] = tf32_of(v.z); p[3] = tf32_of(v.w);
    }
    if (tid < 64)
        Bs[tid] = (bias1 ? bias1[col0 + tid] : 0.f)
                + (bias2 ? bias2[col0 + tid] : 0.f);
    __syncthreads();

    const int lane = tid & 31;
    const int gid  = lane >> 2;    // 0..7
    const int tg   = lane & 3;     // 0..3
    const int warp = tid >> 5;
    const int wm   = warp & 3;     // m warp 0..3
    const int wn   = warp >> 2;    // n warp 0..1

    float acc[2][4][4];
    #pragma unroll
    for (int mt = 0; mt < 2; mt++)
        #pragma unroll
        for (int nt = 0; nt < 4; nt++)
            #pragma unroll
            for (int r = 0; r < 4; r++) acc[mt][nt][r] = 0.f;

    #pragma unroll
    for (int s = 0; s < 8; s++) {
        const int kk = s * 8;
        uint32_t a[2][4];
        #pragma unroll
        for (int mt = 0; mt < 2; mt++) {
            int r = wm * 32 + mt * 16 + gid;
            a[mt][0] = Xs[r * 66 + kk + tg];
            a[mt][1] = Xs[(r + 8) * 66 + kk + tg];
            a[mt][2] = Xs[r * 66 + kk + tg + 4];
            a[mt][3] = Xs[(r + 8) * 66 + kk + tg + 4];
        }
        uint32_t bfr[4][2];
        #pragma unroll
        for (int nt = 0; nt < 4; nt++) {
            int nn = wn * 32 + nt * 8 + gid;
            bfr[nt][0] = Ws[nn * 66 + kk + tg];
            bfr[nt][1] = Ws[nn * 66 + kk + tg + 4];
        }
        #pragma unroll
        for (int mt = 0; mt < 2; mt++)
            #pragma unroll
            for (int nt = 0; nt < 4; nt++)
                mma_tf32(acc[mt][nt], a[mt], bfr[nt]);
    }

    // Epilogue: add bias, store float2 pairs
    #pragma unroll
    for (int mt = 0; mt < 2; mt++) {
        #pragma unroll
        for (int nt = 0; nt < 4; nt++) {
            int rloc = wm * 32 + mt * 16 + gid;
            int cc   = wn * 32 + nt * 8 + 2 * tg;
            float bv0 = Bs[cc], bv1 = Bs[cc + 1];
            #pragma unroll
            for (int half = 0; half < 2; half++) {
                int n = row0 + rloc + half * 8;
                float2 o = make_float2(acc[mt][nt][half * 2] + bv0,
                                       acc[mt][nt][half * 2 + 1] + bv1);
                if (PERM == 0) {
                    *(float2*)(out + (size_t)n * ostride + col0 + cc) = o;
                } else {
                    int b = n & (BB - 1);
                    int t = n >> 9;
                    *(float2*)(out + ((size_t)b * TT + t) * DD + cc) = o;
                }
            }
        }
    }
}

// ---------------------------------------------------------------------------
// LSTM recurrence scan (R6 semantics, cleaned). Block = 128 threads =
// 2 batch elements; grid = 256. Thread t: j = t>>1 (unit), half = t&1
// (k-half for dots; batch for finish). Weights: 4 gate rows of unit j over
// k in [32*half, 32*half+32) packed as 64 u64. Dot: 128 FFMA2 (both batches
// over the k-half). Reduction: ONE shfl_xor(1) per gate with batch-swap.
// Cell state in register; h double-buffered in smem (36-float row padding).
// ONE __syncthreads per step. XGC: xg constant (dec0). SMODE 0/1.
// ---------------------------------------------------------------------------
template<int XGC, int SMODE>
__global__ __launch_bounds__(128, 2) void lstm_scan(
    const float* __restrict__ xg,
    const float* __restrict__ Whh,
    float* __restrict__ hout)
{
    __shared__ float h_sh[2][2][2][36];  // [buf][batch][k-half-bucket][32+4]

    const int tid  = threadIdx.x;
    const int j    = tid >> 1;
    const int half = tid & 1;
    const int b0   = blockIdx.x * 2;
    const int bfin = b0 + half;

    u64 w2[4][16];
    #pragma unroll
    for (int g = 0; g < 4; g++) {
        const ulonglong2* wp =
            (const ulonglong2*)(Whh + (size_t)(g * 64 + j) * 64 + 32 * half);
        #pragma unroll
        for (int i = 0; i < 8; i++) {
            ulonglong2 v = wp[i];
            w2[g][2 * i] = v.x; w2[g][2 * i + 1] = v.y;
        }
    }

    for (int idx = tid; idx < 2 * 2 * 36; idx += 128)
        ((float*)h_sh[0])[idx] = 0.f;

    float xge[4];
    {
        const float* p = xg + (size_t)bfin * GG + j;
        #pragma unroll
        for (int g = 0; g < 4; g++) xge[g] = p[g * 64];
    }
    float c = 0.f;
    __syncthreads();

    for (int t = 0; t < TT; t++) {
        float cur[4];
        #pragma unroll
        for (int g = 0; g < 4; g++) cur[g] = xge[g];
        if (!XGC && t + 1 < TT) {
            const float* p = xg + ((size_t)(t + 1) * BB + bfin) * GG + j;
            #pragma unroll
            for (int g = 0; g < 4; g++) xge[g] = p[g * 64];
        }

        u64 hA[16], hB[16];
        {
            const ulonglong2* pA = (const ulonglong2*)&h_sh[t & 1][0][half][0];
            const ulonglong2* pB = (const ulonglong2*)&h_sh[t & 1][1][half][0];
            #pragma unroll
            for (int i = 0; i < 8; i++) {
                ulonglong2 vA = pA[i];
                ulonglong2 vB = pB[i];
                hA[2*i] = vA.x; hA[2*i+1] = vA.y;
                hB[2*i] = vB.x; hB[2*i+1] = vB.y;
            }
        }

        u64 accA[4] = {0ull, 0ull, 0ull, 0ull};
        u64 accB[4] = {0ull, 0ull, 0ull, 0ull};
        #pragma unroll
        for (int i = 0; i < 16; i++) {
            #pragma unroll
            for (int g = 0; g < 4; g++) {
                accA[g] = ffma2(hA[i], w2[g][i], accA[g]);
                accB[g] = ffma2(hB[i], w2[g][i], accB[g]);
            }
        }

        float tot[4];
        #pragma unroll
        for (int g = 0; g < 4; g++) {
            float2 pA2 = up2(accA[g]);
            float2 pB2 = up2(accB[g]);
            float sA = pA2.x + pA2.y;
            float sB = pB2.x + pB2.y;
            float mine = half ? sB : sA;
            float send = half ? sA : sB;
            tot[g] = mine + __shfl_xor_sync(0xFFFFFFFFu, send, 1) + cur[g];
        }

        float gi = fsigm(tot[0]);
        float gf = fsigm(tot[1]);
        float gc = ftanh(tot[2]);
        float go = fsigm(tot[3]);
        c = fmaf(gf, c, gi * gc);
        float h = go * ftanh(c);

        h_sh[(t + 1) & 1][half][j >> 5][j & 31] = h;
        if (SMODE == 0)
            hout[((size_t)t * BB + bfin) * HH + j] = h;
        if (SMODE == 1 && t == TT - 1)
            hout[(size_t)bfin * HH + j] = h;
        __syncthreads();
    }
}

// ---------------------------------------------------------------------------
extern "C" void kernel_launch(void* const* d_in, const int* in_sizes, int n_in,
                              void* d_out, int out_size)
{
    (void)in_sizes; (void)n_in; (void)out_size;
    const float* x     = (const float*)d_in[0];
    const float* eWih0 = (const float*)d_in[1];
    const float* eWhh0 = (const float*)d_in[2];
    const float* ebih0 = (const float*)d_in[3];
    const float* ebhh0 = (const float*)d_in[4];
    const float* eWih1 = (const float*)d_in[5];
    const float* eWhh1 = (const float*)d_in[6];
    const float* ebih1 = (const float*)d_in[7];
    const float* ebhh1 = (const float*)d_in[8];
    const float* dWih0 = (const float*)d_in[9];
    const float* dWhh0 = (const float*)d_in[10];
    const float* dbih0 = (const float*)d_in[11];
    const float* dbhh0 = (const float*)d_in[12];
    const float* dWih1 = (const float*)d_in[13];
    const float* dWhh1 = (const float*)d_in[14];
    const float* dbih1 = (const float*)d_in[15];
    const float* dbhh1 = (const float*)d_in[16];
    const float* fcW   = (const float*)d_in[17];
    const float* fcb   = (const float*)d_in[18];
    float* out = (float*)d_out;

    float *xgp, *hseqp, *latp, *xgcp;
    cudaGetSymbolAddress((void**)&xgp,   g_xg);
    cudaGetSymbolAddress((void**)&hseqp, g_hseq);
    cudaGetSymbolAddress((void**)&latp,  g_lat);
    cudaGetSymbolAddress((void**)&xgcp,  g_xgc);

    const int smem_tc = (128 * 66 + 64 * 66) * 4 + 64 * 4;  // ~51 KB
    cudaFuncSetAttribute(gemm_tc<0>,
        cudaFuncAttributeMaxDynamicSharedMemorySize, smem_tc);
    cudaFuncSetAttribute(gemm_tc<1>,
        cudaFuncAttributeMaxDynamicSharedMemorySize, smem_tc);

    dim3 gbig(TT * BB / 128, GG / 64);  // (1024, 4)
    dim3 gsm(BB / 128, GG / 64);        // (4, 4)
    dim3 gscan(BB / 2);                 // 256 blocks, 2 batch each, 128 thr
    dim3 gfc(TT * BB / 128, 1);         // (1024, 1)

    // Encoder layer 0
    gemm_tc<0><<<gbig, 256, smem_tc>>>(x, TT * 64, 64, eWih0, ebih0, ebhh0, xgp, GG);
    lstm_scan<0, 0><<<gscan, 128>>>(xgp, eWhh0, hseqp);

    // Encoder layer 1 -> latent
    gemm_tc<0><<<gbig, 256, smem_tc>>>(hseqp, 64, BB * 64, eWih1, ebih1, ebhh1, xgp, GG);
    lstm_scan<0, 1><<<gscan, 128>>>(xgp, eWhh1, latp);

    // Decoder layer 0 (constant input over time)
    gemm_tc<0><<<gsm, 256, smem_tc>>>(latp, 64, 0, dWih0, dbih0, dbhh0, xgcp, GG);
    lstm_scan<1, 0><<<gscan, 128>>>(xgcp, dWhh0, hseqp);

    // Decoder layer 1
    gemm_tc<0><<<gbig, 256, smem_tc>>>(hseqp, 64, BB * 64, dWih1, dbih1, dbhh1, xgp, GG);
    lstm_scan<0, 0><<<gscan, 128>>>(xgp, dWhh1, hseqp);

    // Output projection (permuted store to [B][T][D])
    gemm_tc<1><<<gfc, 256, smem_tc>>>(hseqp, 64, BB * 64, fcW, fcb, nullptr, out, DD);
}